// round 1
// baseline (speedup 1.0000x reference)
#include <cuda_runtime.h>

// Problem constants (fixed shapes from reference)
#define BB   8
#define CC   256
#define HH   64
#define WW   96
#define ND   21        // displacements per axis (-20..20 step 2)
#define NDD  441       // ND*ND
#define MAXD 20

// Tiling
#define GDY  7         // dy values handled per block (3 blocks cover 21)
#define RD   7         // dx values per thread (3 thread-groups cover 21)
#define RX   8         // x values per thread (12 thread-groups cover 96)
#define CK   8         // channels staged in smem per chunk
#define PADW (WW + 2*MAXD)   // 136 columns of padded in2 row
#define BSTRIDE 137          // padded smem stride (odd -> fewer bank conflicts)
#define NACT 252             // 12 * 21 active compute threads
#define NTH  256

__global__ __launch_bounds__(NTH, 2)
void corr_fp32_kernel(const float* __restrict__ in1,
                      const float* __restrict__ in2,
                      float* __restrict__ out)
{
    __shared__ float a_s[CK][WW];          // in1 row chunk
    __shared__ float b_s[CK][GDY][BSTRIDE]; // padded in2 rows for 7 dy

    // block decode: bid = ((b*HH + y)*3 + dyG)
    int bid = blockIdx.x;
    int dyG = bid % 3;
    int y   = (bid / 3) % HH;
    int b   = bid / (3 * HH);
    int jdyBase = dyG * GDY;

    int tid = threadIdx.x;
    bool active = (tid < NACT);

    // thread decode: tid = gx*21 + (gdy*3 + gdx)
    int gx  = tid / (GDY * 3);      // 0..11
    int rem = tid % (GDY * 3);
    int gdy = rem / 3;              // 0..6
    int gdx = rem % 3;              // 0..2
    int xbase   = gx * RX;          // 0,8,...,88
    int jdxBase = gdx * RD;         // 0,7,14
    int off     = xbase + 2 * jdxBase; // base index into padded b row

    float acc[RD][RX];
    #pragma unroll
    for (int t = 0; t < RD; t++)
        #pragma unroll
        for (int i = 0; i < RX; i++)
            acc[t][i] = 0.0f;

    const size_t HW = (size_t)HH * WW;
    const size_t in1_base = ((size_t)b * CC) * HW + (size_t)y * WW;

    for (int c0 = 0; c0 < CC; c0 += CK) {
        __syncthreads();  // previous chunk's compute done before overwrite

        // stage in1 row chunk: CK*WW = 768 floats
        for (int idx = tid; idx < CK * WW; idx += NTH) {
            int c = idx / WW;
            int x = idx % WW;
            a_s[c][x] = in1[in1_base + (size_t)(c0 + c) * HW + x];
        }

        // stage padded in2 rows: CK*GDY*PADW floats (zero-filled OOB)
        for (int idx = tid; idx < CK * GDY * PADW; idx += NTH) {
            int c = idx / (GDY * PADW);
            int r = idx % (GDY * PADW);
            int g = r / PADW;
            int p = r % PADW;
            int row = y + (-MAXD + 2 * (jdyBase + g));
            int col = p - MAXD;
            float v = 0.0f;
            if (row >= 0 && row < HH && col >= 0 && col < WW)
                v = in2[((size_t)(b * CC + c0 + c) * HH + row) * WW + col];
            b_s[c][g][p] = v;
        }

        __syncthreads();

        if (active) {
            #pragma unroll
            for (int c = 0; c < CK; c++) {
                float a8[RX];
                #pragma unroll
                for (int i = 0; i < RX; i++)
                    a8[i] = a_s[c][xbase + i];

                float b20[RX + 2 * (RD - 1)];   // 20 consecutive padded cols
                #pragma unroll
                for (int i = 0; i < RX + 2 * (RD - 1); i++)
                    b20[i] = b_s[c][gdy][off + i];

                #pragma unroll
                for (int t = 0; t < RD; t++)
                    #pragma unroll
                    for (int i = 0; i < RX; i++)
                        acc[t][i] = fmaf(a8[i], b20[i + 2 * t], acc[t][i]);
            }
        }
    }

    if (active) {
        const float scale = 1.0f / (float)CC;
        int jdy = jdyBase + gdy;
        #pragma unroll
        for (int t = 0; t < RD; t++) {
            int d = jdy * ND + (jdxBase + t);
            size_t obase = (((size_t)b * NDD + d) * HH + y) * WW + xbase;
            #pragma unroll
            for (int i = 0; i < RX; i++)
                out[obase + i] = acc[t][i] * scale;
        }
    }
}

extern "C" void kernel_launch(void* const* d_in, const int* in_sizes, int n_in,
                              void* d_out, int out_size)
{
    const float* in1 = (const float*)d_in[0];
    const float* in2 = (const float*)d_in[1];
    float* out = (float*)d_out;

    dim3 grid(BB * HH * 3);
    dim3 block(NTH);
    corr_fp32_kernel<<<grid, block>>>(in1, in2, out);
}

// round 2
// speedup vs baseline: 2.3799x; 2.3799x over previous
#include <cuda_runtime.h>
#include <cstdint>

// Problem constants
#define BB   8
#define CC   256
#define HH   64
#define WW   96
#define ND   21
#define NDD  441
#define MAXD 20

// Tiling
#define GDY  7          // dy per block (3 blocks cover 21)
#define RD   7          // dx per thread
#define RX   8          // x per thread
#define CK   8          // channels per chunk
#define NC   (CC/CK)    // 32 chunks
#define BSTR 140        // padded in2 row stride (floats, 16B-aligned rows)
#define NACT 252
#define NTH  256

#define A_ELEMS (CK*WW)           // 768 floats per stage
#define B_ELEMS (CK*GDY*BSTR)     // 7840 floats per stage
#define STAGE_ELEMS (A_ELEMS + B_ELEMS)    // 8608
#define SMEM_FLOATS (2*STAGE_ELEMS)        // 17216 -> 68864 bytes
#define SMEM_BYTES (SMEM_FLOATS*4)

typedef unsigned long long u64t;

__device__ __forceinline__ void cp_async16(uint32_t saddr, const void* gptr) {
    asm volatile("cp.async.ca.shared.global [%0], [%1], 16;\n" :: "r"(saddr), "l"(gptr));
}
__device__ __forceinline__ void cp_commit() {
    asm volatile("cp.async.commit_group;\n" ::: "memory");
}
template<int N> __device__ __forceinline__ void cp_wait() {
    asm volatile("cp.async.wait_group %0;\n" :: "n"(N) : "memory");
}
__device__ __forceinline__ void fma_f32x2(u64t& d, u64t a, u64t b) {
    asm("fma.rn.f32x2 %0, %1, %2, %0;" : "+l"(d) : "l"(a), "l"(b));
}

__global__ __launch_bounds__(NTH, 2)
void corr_f32x2_kernel(const float* __restrict__ in1,
                       const float* __restrict__ in2,
                       float* __restrict__ out)
{
    extern __shared__ float sm[];

    // block decode: bid = ((b*HH + y)*3 + dyG)
    int bid = blockIdx.x;
    int dyG = bid % 3;
    int y   = (bid / 3) % HH;
    int b   = bid / (3 * HH);
    int jdyBase = dyG * GDY;

    int tid  = threadIdx.x;
    int w    = tid >> 5;          // staging warp = channel within chunk
    int lane = tid & 31;
    bool active = (tid < NACT);

    // compute-thread decode: tid = gx*21 + (gdy*3 + gdx)
    int gx  = tid / (GDY * 3);
    int rem = tid % (GDY * 3);
    int gdy = rem / 3;
    int gdx = rem % 3;
    int xbase   = gx * RX;
    int jdxBase = gdx * RD;
    int off     = xbase + 2 * jdxBase;   // even -> 8B-aligned reads

    // valid in2 rows for this block's 7 dy values
    int  row2v[GDY];
    bool rowok[GDY];
    #pragma unroll
    for (int g = 0; g < GDY; g++) {
        int r = y - MAXD + 2 * (jdyBase + g);
        row2v[g] = r;
        rowok[g] = (unsigned)r < (unsigned)HH;
    }

    const size_t HW = (size_t)HH * WW;

    // zero all smem once (pads + OOB rows stay zero forever)
    for (int i = tid; i < SMEM_FLOATS; i += NTH) sm[i] = 0.0f;
    __syncthreads();

    // per-warp staging base pointers (channel stride = CK per chunk)
    const float* g1row = in1 + ((size_t)b * CC + w) * HW + (size_t)y * WW;
    const float* g2chan = in2 + ((size_t)b * CC + w) * HW;

    // ---- staging lambda: chunk k into stage s ----
    auto stage = [&](int k, int s) {
        if (lane < 24) {
            float* abase = sm + s * STAGE_ELEMS + w * WW;
            const float* p1 = g1row + (size_t)k * CK * HW;
            cp_async16((uint32_t)__cvta_generic_to_shared(abase + lane * 4), p1 + lane * 4);
            float* bbase = sm + s * STAGE_ELEMS + A_ELEMS + w * (GDY * BSTR);
            const float* p2 = g2chan + (size_t)k * CK * HW;
            #pragma unroll
            for (int g = 0; g < GDY; g++) {
                if (rowok[g]) {
                    cp_async16((uint32_t)__cvta_generic_to_shared(bbase + g * BSTR + MAXD + lane * 4),
                               p2 + (size_t)row2v[g] * WW + lane * 4);
                }
            }
        }
    };

    u64t acc[RD][RX/2];
    #pragma unroll
    for (int t = 0; t < RD; t++)
        #pragma unroll
        for (int ip = 0; ip < RX/2; ip++)
            acc[t][ip] = 0ull;

    // prologue
    stage(0, 0);
    cp_commit();

    #pragma unroll 1
    for (int k = 0; k < NC; k++) {
        int s = k & 1;
        if (k + 1 < NC) {
            stage(k + 1, s ^ 1);
            cp_commit();
            cp_wait<1>();
        } else {
            cp_wait<0>();
        }
        __syncthreads();

        if (active) {
            const float* abuf = sm + s * STAGE_ELEMS;
            const float* bbuf = abuf + A_ELEMS;
            #pragma unroll
            for (int c = 0; c < CK; c++) {
                const u64t* ap = (const u64t*)(abuf + c * WW + xbase);
                u64t a2[RX/2];
                #pragma unroll
                for (int ip = 0; ip < RX/2; ip++) a2[ip] = ap[ip];

                const u64t* bp = (const u64t*)(bbuf + c * (GDY * BSTR) + gdy * BSTR + off);
                u64t b2[RX/2 + RD - 1];   // 10
                #pragma unroll
                for (int m = 0; m < RX/2 + RD - 1; m++) b2[m] = bp[m];

                #pragma unroll
                for (int t = 0; t < RD; t++)
                    #pragma unroll
                    for (int ip = 0; ip < RX/2; ip++)
                        fma_f32x2(acc[t][ip], a2[ip], b2[ip + t]);
            }
        }
        __syncthreads();
    }

    if (active) {
        const float scale = 1.0f / (float)CC;
        int jdy = jdyBase + gdy;
        #pragma unroll
        for (int t = 0; t < RD; t++) {
            int d = jdy * ND + (jdxBase + t);
            size_t obase = (((size_t)b * NDD + d) * HH + y) * WW + xbase;
            float2* op = (float2*)(out + obase);
            #pragma unroll
            for (int ip = 0; ip < RX/2; ip++) {
                u64t v = acc[t][ip];
                float lo = __uint_as_float((unsigned)(v & 0xffffffffull));
                float hi = __uint_as_float((unsigned)(v >> 32));
                op[ip] = make_float2(lo * scale, hi * scale);
            }
        }
    }
}

extern "C" void kernel_launch(void* const* d_in, const int* in_sizes, int n_in,
                              void* d_out, int out_size)
{
    const float* in1 = (const float*)d_in[0];
    const float* in2 = (const float*)d_in[1];
    float* out = (float*)d_out;

    cudaFuncSetAttribute(corr_f32x2_kernel,
                         cudaFuncAttributeMaxDynamicSharedMemorySize, SMEM_BYTES);

    dim3 grid(BB * HH * 3);
    dim3 block(NTH);
    corr_f32x2_kernel<<<grid, block, SMEM_BYTES>>>(in1, in2, out);
}